// round 2
// baseline (speedup 1.0000x reference)
#include <cuda_runtime.h>
#include <math.h>

// Problem constants
#define Bq   8
#define Nq   2048
#define Dq   1024
#define Eq   8
#define Hq   4096
#define CAP  320
#define NTOK (Bq*Nq)            // 16384
#define OUT_MAIN ((size_t)NTOK*Dq)  // 16777216

// ---------------- scratch (device globals: allocation-free) ----------------
__device__ int   d_meta[NTOK];               // idx1 | idx2<<4 | keep2<<8
__device__ float d_g1[NTOK];                 // normalized gate1
__device__ float d_g2[NTOK];                 // normalized gate2
__device__ int   d_a1[NTOK];                 // kept1 ? (e<<10|c) : -1
__device__ int   d_a2[NTOK];                 // kept2 ? (e<<10|c) : -1
__device__ float d_proxy[Bq*Eq];             // sum of raw softmax probs per (b,e)
__device__ int   d_slotTok[Eq*Bq*CAP];       // slot -> token (within batch), -1 empty
__device__ float d_h [(size_t)Eq*Bq*CAP*Hq]; // post-GELU hidden  (335 MB)
__device__ float d_eo[(size_t)Eq*Bq*CAP*Dq]; // expert output     ( 84 MB)

// ---------------- init ----------------
__global__ void init_kernel() {
    int t = threadIdx.x;
    if (t < Bq*Eq) d_proxy[t] = 0.f;
}

// ---------------- gating: softmax(x @ wg) top-2 ----------------
__global__ __launch_bounds__(256) void gating_kernel(
    const float* __restrict__ x, const float* __restrict__ wg,
    const float* __restrict__ rnd)
{
    __shared__ float s_wg[Eq][Dq];   // transposed wg, 32KB
    __shared__ float s_proxy[Eq];
    int tid = threadIdx.x;
    for (int f = tid; f < Dq*Eq; f += 256) {
        int d = f >> 3, e = f & 7;
        s_wg[e][d] = wg[f];
    }
    if (tid < Eq) s_proxy[tid] = 0.f;
    __syncthreads();

    int warp = tid >> 5, lane = tid & 31;
    int tok  = blockIdx.x * 8 + warp;
    const float* xp = x + (size_t)tok * Dq;

    float acc[Eq];
    #pragma unroll
    for (int e = 0; e < Eq; ++e) acc[e] = 0.f;

    #pragma unroll 4
    for (int i = 0; i < Dq/32; ++i) {
        float xv = xp[i*32 + lane];
        #pragma unroll
        for (int e = 0; e < Eq; ++e) acc[e] += xv * s_wg[e][i*32 + lane];
    }
    #pragma unroll
    for (int off = 16; off; off >>= 1) {
        #pragma unroll
        for (int e = 0; e < Eq; ++e)
            acc[e] += __shfl_down_sync(0xffffffffu, acc[e], off);
    }

    if (lane == 0) {
        float mx = acc[0];
        #pragma unroll
        for (int e = 1; e < Eq; ++e) mx = fmaxf(mx, acc[e]);
        float raw[Eq]; float s = 0.f;
        #pragma unroll
        for (int e = 0; e < Eq; ++e) { raw[e] = expf(acc[e] - mx); s += raw[e]; }
        float inv = 1.f / s;
        #pragma unroll
        for (int e = 0; e < Eq; ++e) raw[e] *= inv;

        int i1 = 0; float g1 = raw[0];
        #pragma unroll
        for (int e = 1; e < Eq; ++e) if (raw[e] > g1) { g1 = raw[e]; i1 = e; }
        int i2 = -1; float g2 = -1.f;
        #pragma unroll
        for (int e = 0; e < Eq; ++e) if (e != i1 && raw[e] > g2) { g2 = raw[e]; i2 = e; }

        float denom = g1 + g2 + 1e-9f;
        float g1n = g1 / denom, g2n = g2 / denom;
        int keep2 = (rnd[tok] < (g2n / 0.2f)) ? 1 : 0;

        d_meta[tok] = i1 | (i2 << 4) | (keep2 << 8);
        d_g1[tok] = g1n;
        d_g2[tok] = g2n;
        #pragma unroll
        for (int e = 0; e < Eq; ++e) atomicAdd(&s_proxy[e], raw[e]);
    }
    __syncthreads();
    if (tid < Eq) {
        int b = (blockIdx.x * 8) >> 11;
        atomicAdd(&d_proxy[b*Eq + tid], s_proxy[tid]);
    }
}

// ---------------- scan: capacity assignment + loss ----------------
__global__ void scan_kernel(float* __restrict__ dout, int out_size)
{
    __shared__ int   s_meta[2048];
    __shared__ float s_red[64];
    int t = threadIdx.x;      // 64 threads
    int b = t >> 3, e = t & 7;
    int g = e * Bq + b;

    // init my slot slice
    for (int j = 0; j < CAP; ++j) d_slotTok[g*CAP + j] = -1;

    // phase 1: primary-expert positions
    int c1 = 0;
    for (int ch = 0; ch < 8; ++ch) {
        __syncthreads();
        for (int i = t; i < 2048; i += 64) {
            int bb = i >> 8, ii = i & 255;
            s_meta[i] = d_meta[bb*Nq + ch*256 + ii];
        }
        __syncthreads();
        for (int ii = 0; ii < 256; ++ii) {
            int meta = s_meta[b*256 + ii];
            if ((meta & 15) == e) {
                int n = ch*256 + ii;
                if (c1 < CAP) {
                    d_slotTok[g*CAP + c1] = n;
                    d_a1[b*Nq + n] = (e << 10) | c1;
                } else {
                    d_a1[b*Nq + n] = -1;
                }
                c1++;
            }
        }
    }
    int c1raw = c1;
    int pos = (c1 < CAP) ? c1 : CAP;

    // phase 2: secondary-expert positions (offset by truncated primary count)
    for (int ch = 0; ch < 8; ++ch) {
        __syncthreads();
        for (int i = t; i < 2048; i += 64) {
            int bb = i >> 8, ii = i & 255;
            s_meta[i] = d_meta[bb*Nq + ch*256 + ii];
        }
        __syncthreads();
        for (int ii = 0; ii < 256; ++ii) {
            int meta = s_meta[b*256 + ii];
            if (((meta >> 4) & 15) == e) {
                int n = ch*256 + ii;
                if ((meta >> 8) & 1) {
                    if (pos < CAP) {
                        d_slotTok[g*CAP + pos] = n;
                        d_a2[b*Nq + n] = (e << 10) | pos;
                    } else {
                        d_a2[b*Nq + n] = -1;
                    }
                    pos++;
                } else {
                    d_a2[b*Nq + n] = -1;
                }
            }
        }
    }

    // loss = 0.01 * sum_{b,e} (proxy/N) * (count1_raw/N)   [since E*E/(B*E)=1]
    s_red[t] = (d_proxy[b*Eq + e] / (float)Nq) * ((float)c1raw / (float)Nq);
    __syncthreads();
    if (t == 0) {
        float s = 0.f;
        for (int i = 0; i < 64; ++i) s += s_red[i];
        if ((size_t)out_size > OUT_MAIN) dout[OUT_MAIN] = s * 0.01f;
    }
}

// ---------------- grouped FFN GEMM (128x128x8 SIMT, 8x8/thread) ----------------
// PHASE 1: h = gelu(gather(x) @ w1[e] + b1[e]),  K=1024, Ncols=4096
// PHASE 2: eo = h @ w2[e] + b2[e],               K=4096, Ncols=1024
template<int PHASE>
__global__ __launch_bounds__(256) void ffn_gemm(const float* __restrict__ X,
                                                const float* __restrict__ W,
                                                const float* __restrict__ Bias)
{
    constexpr int Kdim  = (PHASE == 1) ? Dq : Hq;
    constexpr int Ncols = (PHASE == 1) ? Hq : Dq;
    __shared__ float As[8][128];
    __shared__ float Bs[8][128];
    __shared__ int   sTok[128];

    const int g  = blockIdx.z;          // e*B + b
    const int e  = g >> 3, b = g & 7;
    const int m0 = blockIdx.x * 128;    // row (capacity slot) tile within group
    const int n0 = blockIdx.y * 128;
    const int tid = threadIdx.x;

    const float* Wp   = W + (size_t)e * Kdim * Ncols;
    float*       Outp = (PHASE == 1) ? d_h : d_eo;

    if (tid < 128) {
        int c = m0 + tid;
        if (c < CAP) sTok[tid] = (PHASE == 1) ? d_slotTok[g*CAP + c] : c;
        else         sTok[tid] = -1;
    }
    __syncthreads();

    float acc[8][8];
    #pragma unroll
    for (int i = 0; i < 8; ++i)
        #pragma unroll
        for (int j = 0; j < 8; ++j) acc[i][j] = 0.f;

    const int tr  = tid >> 4, tc = tid & 15;
    const int lm  = tid >> 1, lk4 = (tid & 1) * 4;
    const int lkB = tid >> 5, lnB = (tid & 31) * 4;

    const int tokA = sTok[lm];
    const float* arow = nullptr;
    if (tokA >= 0)
        arow = (PHASE == 1) ? (X   + ((size_t)(b*Nq)   + tokA) * (size_t)Dq)
                            : (d_h + ((size_t)(g*CAP)  + tokA) * (size_t)Hq);

    for (int kt = 0; kt < Kdim; kt += 8) {
        float4 av = make_float4(0.f, 0.f, 0.f, 0.f);
        if (arow) av = *(const float4*)(arow + kt + lk4);
        As[lk4+0][lm] = av.x; As[lk4+1][lm] = av.y;
        As[lk4+2][lm] = av.z; As[lk4+3][lm] = av.w;
        *(float4*)&Bs[lkB][lnB] =
            *(const float4*)(Wp + (size_t)(kt + lkB) * Ncols + n0 + lnB);
        __syncthreads();

        #pragma unroll
        for (int k = 0; k < 8; ++k) {
            float a[8], bv[8];
            *(float4*)&a[0]  = *(const float4*)&As[k][tr*8];
            *(float4*)&a[4]  = *(const float4*)&As[k][tr*8 + 4];
            *(float4*)&bv[0] = *(const float4*)&Bs[k][tc*8];
            *(float4*)&bv[4] = *(const float4*)&Bs[k][tc*8 + 4];
            #pragma unroll
            for (int i = 0; i < 8; ++i)
                #pragma unroll
                for (int j = 0; j < 8; ++j)
                    acc[i][j] = fmaf(a[i], bv[j], acc[i][j]);
        }
        __syncthreads();
    }

    #pragma unroll
    for (int i = 0; i < 8; ++i) {
        int c = m0 + tr*8 + i;
        if (c < CAP) {
            float* op = Outp + ((size_t)(g*CAP) + c) * Ncols + n0 + tc*8;
            float vbuf[8];
            #pragma unroll
            for (int j = 0; j < 8; ++j) {
                float v = acc[i][j] + Bias[e*Ncols + n0 + tc*8 + j];
                if (PHASE == 1)
                    v = 0.5f * v * (1.0f + erff(v * 0.70710678118654752f));
                vbuf[j] = v;
            }
            *(float4*)op       = *(float4*)&vbuf[0];
            *(float4*)(op + 4) = *(float4*)&vbuf[4];
        }
    }
}

// ---------------- combine: out[b,n,:] = g1*eo[row1] + g2*eo[row2] ----------------
__global__ __launch_bounds__(256) void combine_kernel(float* __restrict__ out)
{
    int tok = blockIdx.x;
    int b   = tok >> 11;
    int a1  = d_a1[tok], a2 = d_a2[tok];
    float g1 = d_g1[tok], g2 = d_g2[tok];
    int off = threadIdx.x * 4;

    float4 v = make_float4(0.f, 0.f, 0.f, 0.f);
    if (a1 >= 0) {
        size_t row = ((size_t)((a1 >> 10) * Bq + b)) * CAP + (a1 & 1023);
        const float4 s = *(const float4*)(d_eo + row * Dq + off);
        v.x = g1 * s.x; v.y = g1 * s.y; v.z = g1 * s.z; v.w = g1 * s.w;
    }
    if (a2 >= 0) {
        size_t row = ((size_t)((a2 >> 10) * Bq + b)) * CAP + (a2 & 1023);
        const float4 s = *(const float4*)(d_eo + row * Dq + off);
        v.x += g2 * s.x; v.y += g2 * s.y; v.z += g2 * s.z; v.w += g2 * s.w;
    }
    *(float4*)(out + (size_t)tok * Dq + off) = v;
}

// ---------------- launch ----------------
extern "C" void kernel_launch(void* const* d_in, const int* in_sizes, int n_in,
                              void* d_out, int out_size)
{
    const float* x  = (const float*)d_in[0];
    const float* wg = (const float*)d_in[1];
    const float* w1 = (const float*)d_in[2];
    const float* b1 = (const float*)d_in[3];
    const float* w2 = (const float*)d_in[4];
    const float* b2 = (const float*)d_in[5];
    const float* rp = (const float*)d_in[6];
    float* out = (float*)d_out;

    init_kernel<<<1, 64>>>();
    gating_kernel<<<NTOK/8, 256>>>(x, wg, rp);
    scan_kernel<<<1, 64>>>(out, out_size);

    dim3 grid1((CAP + 127)/128, Hq/128, Eq*Bq);   // (3, 32, 64)
    ffn_gemm<1><<<grid1, 256>>>(x, w1, b1);
    dim3 grid2((CAP + 127)/128, Dq/128, Eq*Bq);   // (3, 8, 64)
    ffn_gemm<2><<<grid2, 256>>>(nullptr, w2, b2);

    combine_kernel<<<NTOK, 256>>>(out);
}

// round 4
// speedup vs baseline: 4.0937x; 4.0937x over previous
#include <cuda_runtime.h>
#include <math.h>
#include <cstdint>

#define Bq   8
#define Nq   2048
#define Dq   1024
#define Eq   8
#define Hq   4096
#define CAP  320
#define NTOK (Bq*Nq)
#define OUT_MAIN ((size_t)NTOK*Dq)

__device__ int   d_meta[NTOK];
__device__ float d_g1[NTOK];
__device__ float d_g2[NTOK];
__device__ int   d_a1[NTOK];
__device__ int   d_a2[NTOK];
__device__ float d_proxy[Bq*Eq];
__device__ int   d_slotTok[Eq*Bq*CAP];
__device__ float d_h [(size_t)Eq*Bq*CAP*Hq];
__device__ float d_eo[(size_t)Eq*Bq*CAP*Dq];

// ---------------- helpers ----------------
__device__ __forceinline__ uint32_t f2tf32(float x) {
    uint32_t r;
    asm("cvt.rna.tf32.f32 %0, %1;" : "=r"(r) : "f"(x));
    return r;
}
__device__ __forceinline__ void mma_tf32(float* d, const uint32_t* a, const uint32_t* b) {
    asm volatile(
        "mma.sync.aligned.m16n8k8.row.col.f32.tf32.tf32.f32 "
        "{%0,%1,%2,%3}, {%4,%5,%6,%7}, {%8,%9}, {%0,%1,%2,%3};\n"
        : "+f"(d[0]), "+f"(d[1]), "+f"(d[2]), "+f"(d[3])
        : "r"(a[0]), "r"(a[1]), "r"(a[2]), "r"(a[3]), "r"(b[0]), "r"(b[1]));
}

// ---------------- init ----------------
__global__ void init_kernel() {
    int t = threadIdx.x;
    if (t < Bq*Eq) d_proxy[t] = 0.f;
}

// ---------------- gating ----------------
__global__ __launch_bounds__(256) void gating_kernel(
    const float* __restrict__ x, const float* __restrict__ wg,
    const float* __restrict__ rnd)
{
    __shared__ float s_wg[Eq][Dq];
    __shared__ float s_proxy[Eq];
    int tid = threadIdx.x;
    for (int f = tid; f < Dq*Eq; f += 256) {
        int d = f >> 3, e = f & 7;
        s_wg[e][d] = wg[f];
    }
    if (tid < Eq) s_proxy[tid] = 0.f;
    __syncthreads();

    int warp = tid >> 5, lane = tid & 31;
    int tok  = blockIdx.x * 8 + warp;
    const float* xp = x + (size_t)tok * Dq;

    float acc[Eq];
    #pragma unroll
    for (int e = 0; e < Eq; ++e) acc[e] = 0.f;
    #pragma unroll 4
    for (int i = 0; i < Dq/32; ++i) {
        float xv = xp[i*32 + lane];
        #pragma unroll
        for (int e = 0; e < Eq; ++e) acc[e] += xv * s_wg[e][i*32 + lane];
    }
    #pragma unroll
    for (int off = 16; off; off >>= 1)
        #pragma unroll
        for (int e = 0; e < Eq; ++e)
            acc[e] += __shfl_down_sync(0xffffffffu, acc[e], off);

    if (lane == 0) {
        float mx = acc[0];
        #pragma unroll
        for (int e = 1; e < Eq; ++e) mx = fmaxf(mx, acc[e]);
        float raw[Eq]; float s = 0.f;
        #pragma unroll
        for (int e = 0; e < Eq; ++e) { raw[e] = expf(acc[e] - mx); s += raw[e]; }
        float inv = 1.f / s;
        #pragma unroll
        for (int e = 0; e < Eq; ++e) raw[e] *= inv;
        int i1 = 0; float g1 = raw[0];
        #pragma unroll
        for (int e = 1; e < Eq; ++e) if (raw[e] > g1) { g1 = raw[e]; i1 = e; }
        int i2 = -1; float g2 = -1.f;
        #pragma unroll
        for (int e = 0; e < Eq; ++e) if (e != i1 && raw[e] > g2) { g2 = raw[e]; i2 = e; }
        float denom = g1 + g2 + 1e-9f;
        float g1n = g1 / denom, g2n = g2 / denom;
        int keep2 = (rnd[tok] < (g2n / 0.2f)) ? 1 : 0;
        d_meta[tok] = i1 | (i2 << 4) | (keep2 << 8);
        d_g1[tok] = g1n;
        d_g2[tok] = g2n;
        #pragma unroll
        for (int e = 0; e < Eq; ++e) atomicAdd(&s_proxy[e], raw[e]);
    }
    __syncthreads();
    if (tid < Eq) {
        int b = (blockIdx.x * 8) >> 11;
        atomicAdd(&d_proxy[b*Eq + tid], s_proxy[tid]);
    }
}

// ---------------- scan ----------------
__global__ void scan_kernel(float* __restrict__ dout, int out_size)
{
    __shared__ int   s_meta[2048];
    __shared__ float s_red[64];
    int t = threadIdx.x;
    int b = t >> 3, e = t & 7;
    int g = e * Bq + b;
    for (int j = 0; j < CAP; ++j) d_slotTok[g*CAP + j] = -1;
    int c1 = 0;
    for (int ch = 0; ch < 8; ++ch) {
        __syncthreads();
        for (int i = t; i < 2048; i += 64) {
            int bb = i >> 8, ii = i & 255;
            s_meta[i] = d_meta[bb*Nq + ch*256 + ii];
        }
        __syncthreads();
        for (int ii = 0; ii < 256; ++ii) {
            int meta = s_meta[b*256 + ii];
            if ((meta & 15) == e) {
                int n = ch*256 + ii;
                if (c1 < CAP) {
                    d_slotTok[g*CAP + c1] = n;
                    d_a1[b*Nq + n] = (e << 10) | c1;
                } else d_a1[b*Nq + n] = -1;
                c1++;
            }
        }
    }
    int c1raw = c1;
    int pos = (c1 < CAP) ? c1 : CAP;
    for (int ch = 0; ch < 8; ++ch) {
        __syncthreads();
        for (int i = t; i < 2048; i += 64) {
            int bb = i >> 8, ii = i & 255;
            s_meta[i] = d_meta[bb*Nq + ch*256 + ii];
        }
        __syncthreads();
        for (int ii = 0; ii < 256; ++ii) {
            int meta = s_meta[b*256 + ii];
            if (((meta >> 4) & 15) == e) {
                int n = ch*256 + ii;
                if ((meta >> 8) & 1) {
                    if (pos < CAP) {
                        d_slotTok[g*CAP + pos] = n;
                        d_a2[b*Nq + n] = (e << 10) | pos;
                    } else d_a2[b*Nq + n] = -1;
                    pos++;
                } else d_a2[b*Nq + n] = -1;
            }
        }
    }
    s_red[t] = (d_proxy[b*Eq + e] / (float)Nq) * ((float)c1raw / (float)Nq);
    __syncthreads();
    if (t == 0) {
        float s = 0.f;
        for (int i = 0; i < 64; ++i) s += s_red[i];
        if ((size_t)out_size > OUT_MAIN) dout[OUT_MAIN] = s * 0.01f;
    }
}

// ---------------- tf32 mma.sync grouped GEMM ----------------
// CTA 128x128, K in 32-chunks, double-buffered SMEM + register prefetch.
// 8 warps (2m x 4n), warp tile 64x32, mma m16n8k8.
// SMEM: sA[2][128*32] u32 (tf32), sB[2][32*128] u32, sPtr[128], sBias[128].
// A swizzle: idx = r*32 + (k ^ 4*(r&7)).  B swizzle: idx = k*128 + ((n + 8k)&127).
#define SMEM_FFN (32768 + 32768 + 1024 + 512)

template<int PHASE>
__global__ __launch_bounds__(256, 1) void ffn_mma(const float* __restrict__ X,
                                                  const float* __restrict__ W,
                                                  const float* __restrict__ Bias)
{
    constexpr int Kdim  = (PHASE == 1) ? Dq : Hq;
    constexpr int Ncols = (PHASE == 1) ? Hq : Dq;
    constexpr int NCH   = Kdim / 32;

    extern __shared__ char smem[];
    uint32_t*     sA    = (uint32_t*)smem;              // 2 x 4096 u32
    uint32_t*     sB    = (uint32_t*)(smem + 32768);    // 2 x 4096 u32
    const float** sPtr  = (const float**)(smem + 65536);
    float*        sBias = (float*)(smem + 66560);

    const int tid = threadIdx.x;
    const int wid = tid >> 5, lane = tid & 31;
    const int g8  = lane >> 2, tg = lane & 3;
    const int n0  = blockIdx.x * 128;
    const int m0  = blockIdx.y * 128;
    const int grp = blockIdx.z;
    const int e   = grp >> 3, b = grp & 7;
    const int wm  = wid & 1, wn = wid >> 1;

    if (tid < 128) {
        int c = m0 + tid;
        const float* p = nullptr;
        if (c < CAP) {
            if (PHASE == 1) {
                int tok = d_slotTok[grp*CAP + c];
                if (tok >= 0) p = X + ((size_t)(b*Nq) + tok) * Dq;
            } else {
                p = d_h + ((size_t)grp*CAP + c) * Hq;
            }
        }
        sPtr[tid]  = p;
        sBias[tid] = Bias[(size_t)e * Ncols + n0 + tid];
    }
    __syncthreads();

    // load geometry
    const int ar  = tid >> 1;          // A row 0..127
    const int afb = (tid & 1) * 4;     // A float4-slot base (slots 0..7 per row)
    const float* aptr = sPtr[ar];
    const int br  = tid >> 3;          // B k-row 0..31
    const int bfb = tid & 7;           // B float4-slot base pattern
    const float* Wg = W + (size_t)e * Kdim * Ncols + n0;

    float4 rA[4], rB[4];

    #define LDA(ch) do { \
        _Pragma("unroll") \
        for (int i = 0; i < 4; ++i) { \
            if (aptr) rA[i] = *(const float4*)(aptr + (ch)*32 + (afb + i)*4); \
            else      rA[i] = make_float4(0.f, 0.f, 0.f, 0.f); \
        } } while (0)
    #define LDB(ch) do { \
        _Pragma("unroll") \
        for (int i = 0; i < 4; ++i) \
            rB[i] = *(const float4*)(Wg + (size_t)((ch)*32 + br) * Ncols + (bfb + 8*i)*4); \
        } while (0)
    #define STA(buf) do { \
        _Pragma("unroll") \
        for (int i = 0; i < 4; ++i) { \
            int f = afb + i; \
            uint32_t* d = sA + (buf)*4096 + ar*32 + 4*(f ^ (ar & 7)); \
            d[0] = f2tf32(rA[i].x); d[1] = f2tf32(rA[i].y); \
            d[2] = f2tf32(rA[i].z); d[3] = f2tf32(rA[i].w); \
        } } while (0)
    #define STB(buf) do { \
        _Pragma("unroll") \
        for (int i = 0; i < 4; ++i) { \
            int f = bfb + 8*i; \
            uint32_t* d = sB + (buf)*4096 + br*128 + 4*((f + 2*br) & 31); \
            d[0] = f2tf32(rB[i].x); d[1] = f2tf32(rB[i].y); \
            d[2] = f2tf32(rB[i].z); d[3] = f2tf32(rB[i].w); \
        } } while (0)

    float acc[4][4][4];
    #pragma unroll
    for (int mi = 0; mi < 4; ++mi)
        #pragma unroll
        for (int ni = 0; ni < 4; ++ni)
            #pragma unroll
            for (int q = 0; q < 4; ++q) acc[mi][ni][q] = 0.f;

    LDA(0); LDB(0);
    STA(0); STB(0);
    __syncthreads();

    for (int ch = 0; ch < NCH; ++ch) {
        const int buf = ch & 1;
        if (ch + 1 < NCH) { LDA(ch + 1); LDB(ch + 1); }

        const uint32_t* bufA = sA + buf*4096;
        const uint32_t* bufB = sB + buf*4096;
        #pragma unroll
        for (int ks = 0; ks < 4; ++ks) {
            const int k0 = ks*8 + tg;
            const int k1 = k0 + 4;
            uint32_t af[4][4], bf[4][2];
            #pragma unroll
            for (int mi = 0; mi < 4; ++mi) {
                const uint32_t* base = bufA + (wm*64 + mi*16 + g8) * 32;
                const int sw = 4 * g8;            // (row & 7) == g8 for both halves
                af[mi][0] = base[k0 ^ sw];
                af[mi][1] = base[256 + (k0 ^ sw)];
                af[mi][2] = base[k1 ^ sw];
                af[mi][3] = base[256 + (k1 ^ sw)];
            }
            #pragma unroll
            for (int ni = 0; ni < 4; ++ni) {
                const int n = wn*32 + ni*8 + g8;
                bf[ni][0] = bufB[k0*128 + ((n + 8*k0) & 127)];
                bf[ni][1] = bufB[k1*128 + ((n + 8*k1) & 127)];
            }
            #pragma unroll
            for (int mi = 0; mi < 4; ++mi)
                #pragma unroll
                for (int ni = 0; ni < 4; ++ni)
                    mma_tf32(acc[mi][ni], af[mi], bf[ni]);
        }

        if (ch + 1 < NCH) { STA((ch + 1) & 1); STB((ch + 1) & 1); }
        __syncthreads();
    }

    // epilogue: bias (+GELU phase1), direct float2 stores
    float* Outp = (PHASE == 1) ? d_h : d_eo;
    #pragma unroll
    for (int mi = 0; mi < 4; ++mi) {
        #pragma unroll
        for (int h = 0; h < 2; ++h) {
            int c = m0 + wm*64 + mi*16 + g8 + h*8;
            if (c < CAP) {
                float* orow = Outp + ((size_t)grp*CAP + c) * Ncols + n0;
                #pragma unroll
                for (int ni = 0; ni < 4; ++ni) {
                    int col = wn*32 + ni*8 + 2*tg;
                    float v0 = acc[mi][ni][2*h]     + sBias[col];
                    float v1 = acc[mi][ni][2*h + 1] + sBias[col + 1];
                    if (PHASE == 1) {
                        v0 = 0.5f * v0 * (1.0f + erff(v0 * 0.70710678118654752f));
                        v1 = 0.5f * v1 * (1.0f + erff(v1 * 0.70710678118654752f));
                    }
                    float2 v = make_float2(v0, v1);
                    *(float2*)(orow + col) = v;
                }
            }
        }
    }
    #undef LDA
    #undef LDB
    #undef STA
    #undef STB
}

// ---------------- combine ----------------
__global__ __launch_bounds__(256) void combine_kernel(float* __restrict__ out)
{
    int tok = blockIdx.x;
    int b   = tok >> 11;
    int a1  = d_a1[tok], a2 = d_a2[tok];
    float g1 = d_g1[tok], g2 = d_g2[tok];
    int off = threadIdx.x * 4;

    float4 v = make_float4(0.f, 0.f, 0.f, 0.f);
    if (a1 >= 0) {
        size_t row = ((size_t)((a1 >> 10) * Bq + b)) * CAP + (a1 & 1023);
        const float4 s = *(const float4*)(d_eo + row * Dq + off);
        v.x = g1 * s.x; v.y = g1 * s.y; v.z = g1 * s.z; v.w = g1 * s.w;
    }
    if (a2 >= 0) {
        size_t row = ((size_t)((a2 >> 10) * Bq + b)) * CAP + (a2 & 1023);
        const float4 s = *(const float4*)(d_eo + row * Dq + off);
        v.x += g2 * s.x; v.y += g2 * s.y; v.z += g2 * s.z; v.w += g2 * s.w;
    }
    *(float4*)(out + (size_t)tok * Dq + off) = v;
}

// ---------------- launch ----------------
extern "C" void kernel_launch(void* const* d_in, const int* in_sizes, int n_in,
                              void* d_out, int out_size)
{
    const float* x  = (const float*)d_in[0];
    const float* wg = (const float*)d_in[1];
    const float* w1 = (const float*)d_in[2];
    const float* b1 = (const float*)d_in[3];
    const float* w2 = (const float*)d_in[4];
    const float* b2 = (const float*)d_in[5];
    const float* rp = (const float*)d_in[6];
    float* out = (float*)d_out;

    cudaFuncSetAttribute(ffn_mma<1>, cudaFuncAttributeMaxDynamicSharedMemorySize, SMEM_FFN);
    cudaFuncSetAttribute(ffn_mma<2>, cudaFuncAttributeMaxDynamicSharedMemorySize, SMEM_FFN);

    init_kernel<<<1, 64>>>();
    gating_kernel<<<NTOK/8, 256>>>(x, wg, rp);
    scan_kernel<<<1, 64>>>(out, out_size);

    ffn_mma<1><<<dim3(Hq/128, 3, Eq*Bq), 256, SMEM_FFN>>>(x, w1, b1);
    ffn_mma<2><<<dim3(Dq/128, 3, Eq*Bq), 256, SMEM_FFN>>>(nullptr, w2, b2);

    combine_kernel<<<NTOK, 256>>>(out);
}

// round 5
// speedup vs baseline: 4.6022x; 1.1242x over previous
#include <cuda_runtime.h>
#include <math.h>
#include <cstdint>

#define Bq   8
#define Nq   2048
#define Dq   1024
#define Eq   8
#define Hq   4096
#define CAP  320
#define NTOK (Bq*Nq)
#define OUT_MAIN ((size_t)NTOK*Dq)

__device__ int   d_meta[NTOK];
__device__ float d_g1[NTOK];
__device__ float d_g2[NTOK];
__device__ int   d_a1[NTOK];
__device__ int   d_a2[NTOK];
__device__ float d_proxy[Bq*Eq];
__device__ int   d_slotTok[Eq*Bq*CAP];
__device__ float d_h [(size_t)Eq*Bq*CAP*Hq];
__device__ float d_eo[(size_t)Eq*Bq*CAP*Dq];

// ---------------- helpers ----------------
__device__ __forceinline__ uint32_t smem_u32(const void* p) {
    uint32_t a;
    asm("{ .reg .u64 t; cvta.to.shared.u64 t, %1; cvt.u32.u64 %0, t; }" : "=r"(a) : "l"(p));
    return a;
}
__device__ __forceinline__ uint32_t f2tf32(float x) {
    uint32_t r;
    asm("cvt.rna.tf32.f32 %0, %1;" : "=r"(r) : "f"(x));
    return r;
}
__device__ __forceinline__ void mma_tf32(float* d, const uint32_t* a, const uint32_t* b) {
    asm volatile(
        "mma.sync.aligned.m16n8k8.row.col.f32.tf32.tf32.f32 "
        "{%0,%1,%2,%3}, {%4,%5,%6,%7}, {%8,%9}, {%0,%1,%2,%3};\n"
        : "+f"(d[0]), "+f"(d[1]), "+f"(d[2]), "+f"(d[3])
        : "r"(a[0]), "r"(a[1]), "r"(a[2]), "r"(a[3]), "r"(b[0]), "r"(b[1]));
}
__device__ __forceinline__ void ldsm4(uint32_t* r, uint32_t addr) {
    asm volatile("ldmatrix.sync.aligned.m8n8.x4.shared.b16 {%0,%1,%2,%3}, [%4];"
        : "=r"(r[0]), "=r"(r[1]), "=r"(r[2]), "=r"(r[3]) : "r"(addr));
}

// ---------------- init ----------------
__global__ void init_kernel() {
    int t = threadIdx.x;
    if (t < Bq*Eq) d_proxy[t] = 0.f;
}

// ---------------- gating ----------------
__global__ __launch_bounds__(256) void gating_kernel(
    const float* __restrict__ x, const float* __restrict__ wg,
    const float* __restrict__ rnd)
{
    __shared__ float s_wg[Eq][Dq];
    __shared__ float s_proxy[Eq];
    int tid = threadIdx.x;
    for (int f = tid; f < Dq*Eq; f += 256) {
        int d = f >> 3, e = f & 7;
        s_wg[e][d] = wg[f];
    }
    if (tid < Eq) s_proxy[tid] = 0.f;
    __syncthreads();

    int warp = tid >> 5, lane = tid & 31;
    int tok  = blockIdx.x * 8 + warp;
    const float* xp = x + (size_t)tok * Dq;

    float acc[Eq];
    #pragma unroll
    for (int e = 0; e < Eq; ++e) acc[e] = 0.f;
    #pragma unroll 4
    for (int i = 0; i < Dq/32; ++i) {
        float xv = xp[i*32 + lane];
        #pragma unroll
        for (int e = 0; e < Eq; ++e) acc[e] += xv * s_wg[e][i*32 + lane];
    }
    #pragma unroll
    for (int off = 16; off; off >>= 1)
        #pragma unroll
        for (int e = 0; e < Eq; ++e)
            acc[e] += __shfl_down_sync(0xffffffffu, acc[e], off);

    if (lane == 0) {
        float mx = acc[0];
        #pragma unroll
        for (int e = 1; e < Eq; ++e) mx = fmaxf(mx, acc[e]);
        float raw[Eq]; float s = 0.f;
        #pragma unroll
        for (int e = 0; e < Eq; ++e) { raw[e] = expf(acc[e] - mx); s += raw[e]; }
        float inv = 1.f / s;
        #pragma unroll
        for (int e = 0; e < Eq; ++e) raw[e] *= inv;
        int i1 = 0; float g1 = raw[0];
        #pragma unroll
        for (int e = 1; e < Eq; ++e) if (raw[e] > g1) { g1 = raw[e]; i1 = e; }
        int i2 = -1; float g2 = -1.f;
        #pragma unroll
        for (int e = 0; e < Eq; ++e) if (e != i1 && raw[e] > g2) { g2 = raw[e]; i2 = e; }
        float denom = g1 + g2 + 1e-9f;
        float g1n = g1 / denom, g2n = g2 / denom;
        int keep2 = (rnd[tok] < (g2n / 0.2f)) ? 1 : 0;
        d_meta[tok] = i1 | (i2 << 4) | (keep2 << 8);
        d_g1[tok] = g1n;
        d_g2[tok] = g2n;
        #pragma unroll
        for (int e = 0; e < Eq; ++e) atomicAdd(&s_proxy[e], raw[e]);
    }
    __syncthreads();
    if (tid < Eq) {
        int b = (blockIdx.x * 8) >> 11;
        atomicAdd(&d_proxy[b*Eq + tid], s_proxy[tid]);
    }
}

// ---------------- scan ----------------
__global__ void scan_kernel(float* __restrict__ dout, int out_size)
{
    __shared__ int   s_meta[2048];
    __shared__ float s_red[64];
    int t = threadIdx.x;
    int b = t >> 3, e = t & 7;
    int g = e * Bq + b;
    for (int j = 0; j < CAP; ++j) d_slotTok[g*CAP + j] = -1;
    int c1 = 0;
    for (int ch = 0; ch < 8; ++ch) {
        __syncthreads();
        for (int i = t; i < 2048; i += 64) {
            int bb = i >> 8, ii = i & 255;
            s_meta[i] = d_meta[bb*Nq + ch*256 + ii];
        }
        __syncthreads();
        for (int ii = 0; ii < 256; ++ii) {
            int meta = s_meta[b*256 + ii];
            if ((meta & 15) == e) {
                int n = ch*256 + ii;
                if (c1 < CAP) {
                    d_slotTok[g*CAP + c1] = n;
                    d_a1[b*Nq + n] = (e << 10) | c1;
                } else d_a1[b*Nq + n] = -1;
                c1++;
            }
        }
    }
    int c1raw = c1;
    int pos = (c1 < CAP) ? c1 : CAP;
    for (int ch = 0; ch < 8; ++ch) {
        __syncthreads();
        for (int i = t; i < 2048; i += 64) {
            int bb = i >> 8, ii = i & 255;
            s_meta[i] = d_meta[bb*Nq + ch*256 + ii];
        }
        __syncthreads();
        for (int ii = 0; ii < 256; ++ii) {
            int meta = s_meta[b*256 + ii];
            if (((meta >> 4) & 15) == e) {
                int n = ch*256 + ii;
                if ((meta >> 8) & 1) {
                    if (pos < CAP) {
                        d_slotTok[g*CAP + pos] = n;
                        d_a2[b*Nq + n] = (e << 10) | pos;
                    } else d_a2[b*Nq + n] = -1;
                    pos++;
                } else d_a2[b*Nq + n] = -1;
            }
        }
    }
    s_red[t] = (d_proxy[b*Eq + e] / (float)Nq) * ((float)c1raw / (float)Nq);
    __syncthreads();
    if (t == 0) {
        float s = 0.f;
        for (int i = 0; i < 64; ++i) s += s_red[i];
        if ((size_t)out_size > OUT_MAIN) dout[OUT_MAIN] = s * 0.01f;
    }
}

// ---------------- tf32 mma.sync grouped GEMM (ldmatrix fragments) ----------------
// CTA 128x128, K in 32-chunks, double-buffered SMEM, 8 warps (2m x 4n), warp 64x32.
// SMEM bytes: sA[2][16384] @0  (A[row][k] 128x32 tf32, slot swizzle f^(row&7))
//             sB[2][16384] @32768 (B[n][k] 128x32 tf32, same swizzle)
//             sPtr @65536 (1KB), sBias @66560 (512B)
#define SMEM_FFN 67072

template<int PHASE>
__global__ __launch_bounds__(256, 1) void ffn_mma(const float* __restrict__ X,
                                                  const float* __restrict__ W,
                                                  const float* __restrict__ Bias)
{
    constexpr int Kdim  = (PHASE == 1) ? Dq : Hq;
    constexpr int Ncols = (PHASE == 1) ? Hq : Dq;
    constexpr int NCH   = Kdim / 32;

    extern __shared__ char smem[];
    const float** sPtr  = (const float**)(smem + 65536);
    float*        sBias = (float*)(smem + 66560);

    const int tid  = threadIdx.x;
    const int wid  = tid >> 5, lane = tid & 31;
    const int g8   = lane >> 2, tg = lane & 3;
    const int n0   = blockIdx.x * 128;
    const int m0   = blockIdx.y * 128;
    const int grp  = blockIdx.z;
    const int e    = grp >> 3, b = grp & 7;
    const int wm   = wid & 1, wn = wid >> 1;
    const bool active = (m0 + wm*64) < CAP;   // skip all-padding half-tiles

    if (tid < 128) {
        int c = m0 + tid;
        const float* p = nullptr;
        if (c < CAP) {
            if (PHASE == 1) {
                int tok = d_slotTok[grp*CAP + c];
                if (tok >= 0) p = X + ((size_t)(b*Nq) + tok) * Dq;
            } else {
                p = d_h + ((size_t)grp*CAP + c) * Hq;
            }
        }
        sPtr[tid]  = p;
        sBias[tid] = Bias[(size_t)e * Ncols + n0 + tid];
    }
    __syncthreads();

    const uint32_t sb = smem_u32(smem);

    // ldmatrix per-lane address bases (A: rows within warp m-slab; B: n-rows)
    const int hiA = lane >> 4;
    const uint32_t aBase = sb + (uint32_t)(wm*64 + ((lane>>3)&1)*8 + (lane&7)) * 128u;
    const uint32_t bBase = sb + 32768u + (uint32_t)(wn*32 + (lane>>4)*8 + (lane&7)) * 128u;
    uint32_t aSw[4], bSw[4];
    #pragma unroll
    for (int ks = 0; ks < 4; ++ks) {
        aSw[ks] = 16u * (uint32_t)((2*ks + hiA) ^ (lane & 7));
        bSw[ks] = 16u * (uint32_t)((2*ks + ((lane>>3)&1)) ^ (lane & 7));
    }

    // global-load / SMEM-store geometry
    const int ar  = tid >> 1;           // A row 0..127
    const int afb = (tid & 1) * 4;      // A 16B-slot base
    const float* aptr = sPtr[ar];
    const int bn  = tid & 127;          // B n-column
    const int bkq = tid >> 7;           // 0/1
    const float* Wg = W + (size_t)e * Kdim * Ncols + n0;

    float4 rA[4], rB[4];

    #define LDA(ch) do { \
        _Pragma("unroll") \
        for (int i = 0; i < 4; ++i) { \
            if (aptr) rA[i] = *(const float4*)(aptr + (ch)*32 + (afb + i)*4); \
            else      rA[i] = make_float4(0.f, 0.f, 0.f, 0.f); \
        } } while (0)
    #define LDB(ch) do { \
        _Pragma("unroll") \
        for (int i = 0; i < 4; ++i) { \
            const float* wp = Wg + (size_t)((ch)*32 + (i*2 + bkq)*4) * Ncols + bn; \
            rB[i].x = wp[0]; \
            rB[i].y = wp[Ncols]; \
            rB[i].z = wp[(size_t)2*Ncols]; \
            rB[i].w = wp[(size_t)3*Ncols]; \
        } } while (0)
    #define STA(buf) do { \
        _Pragma("unroll") \
        for (int i = 0; i < 4; ++i) { \
            int f = afb + i; \
            uint32_t* d = (uint32_t*)(smem + (buf)*16384 + ar*128 + 16*(f ^ (ar & 7))); \
            d[0] = f2tf32(rA[i].x); d[1] = f2tf32(rA[i].y); \
            d[2] = f2tf32(rA[i].z); d[3] = f2tf32(rA[i].w); \
        } } while (0)
    #define STB(buf) do { \
        _Pragma("unroll") \
        for (int i = 0; i < 4; ++i) { \
            int kq = i*2 + bkq; \
            uint32_t* d = (uint32_t*)(smem + 32768 + (buf)*16384 + bn*128 + 16*(kq ^ (bn & 7))); \
            d[0] = f2tf32(rB[i].x); d[1] = f2tf32(rB[i].y); \
            d[2] = f2tf32(rB[i].z); d[3] = f2tf32(rB[i].w); \
        } } while (0)

    float acc[4][4][4];
    #pragma unroll
    for (int mi = 0; mi < 4; ++mi)
        #pragma unroll
        for (int ni = 0; ni < 4; ++ni)
            #pragma unroll
            for (int q = 0; q < 4; ++q) acc[mi][ni][q] = 0.f;

    LDA(0); LDB(0);
    STA(0); STB(0);
    __syncthreads();

    for (int ch = 0; ch < NCH; ++ch) {
        const uint32_t bufOff = (ch & 1) ? 16384u : 0u;
        if (ch + 1 < NCH) { LDA(ch + 1); LDB(ch + 1); }

        if (active) {
            #pragma unroll
            for (int ks = 0; ks < 4; ++ks) {
                uint32_t af[4][4], bf[2][4];
                const uint32_t ao = bufOff + aSw[ks];
                const uint32_t bo = bufOff + bSw[ks];
                #pragma unroll
                for (int mi = 0; mi < 4; ++mi)
                    ldsm4(af[mi], aBase + (uint32_t)(mi*2048) + ao);
                ldsm4(bf[0], bBase + bo);            // ni 0,1
                ldsm4(bf[1], bBase + 2048u + bo);    // ni 2,3
                #pragma unroll
                for (int mi = 0; mi < 4; ++mi) {
                    mma_tf32(acc[mi][0], af[mi], &bf[0][0]);
                    mma_tf32(acc[mi][1], af[mi], &bf[0][2]);
                    mma_tf32(acc[mi][2], af[mi], &bf[1][0]);
                    mma_tf32(acc[mi][3], af[mi], &bf[1][2]);
                }
            }
        }

        if (ch + 1 < NCH) { STA((ch + 1) & 1); STB((ch + 1) & 1); }
        __syncthreads();
    }

    // epilogue: bias (+GELU phase1), direct float2 stores
    float* Outp = (PHASE == 1) ? d_h : d_eo;
    #pragma unroll
    for (int mi = 0; mi < 4; ++mi) {
        #pragma unroll
        for (int h = 0; h < 2; ++h) {
            int c = m0 + wm*64 + mi*16 + g8 + h*8;
            if (c < CAP) {
                float* orow = Outp + ((size_t)grp*CAP + c) * Ncols + n0;
                #pragma unroll
                for (int ni = 0; ni < 4; ++ni) {
                    int col = wn*32 + ni*8 + 2*tg;
                    float v0 = acc[mi][ni][2*h]     + sBias[col];
                    float v1 = acc[mi][ni][2*h + 1] + sBias[col + 1];
                    if (PHASE == 1) {
                        v0 = 0.5f * v0 * (1.0f + erff(v0 * 0.70710678118654752f));
                        v1 = 0.5f * v1 * (1.0f + erff(v1 * 0.70710678118654752f));
                    }
                    float2 v = make_float2(v0, v1);
                    *(float2*)(orow + col) = v;
                }
            }
        }
    }
    #undef LDA
    #undef LDB
    #undef STA
    #undef STB
}

// ---------------- combine ----------------
__global__ __launch_bounds__(256) void combine_kernel(float* __restrict__ out)
{
    int tok = blockIdx.x;
    int b   = tok >> 11;
    int a1  = d_a1[tok], a2 = d_a2[tok];
    float g1 = d_g1[tok], g2 = d_g2[tok];
    int off = threadIdx.x * 4;

    float4 v = make_float4(0.f, 0.f, 0.f, 0.f);
    if (a1 >= 0) {
        size_t row = ((size_t)((a1 >> 10) * Bq + b)) * CAP + (a1 & 1023);
        const float4 s = *(const float4*)(d_eo + row * Dq + off);
        v.x = g1 * s.x; v.y = g1 * s.y; v.z = g1 * s.z; v.w = g1 * s.w;
    }
    if (a2 >= 0) {
        size_t row = ((size_t)((a2 >> 10) * Bq + b)) * CAP + (a2 & 1023);
        const float4 s = *(const float4*)(d_eo + row * Dq + off);
        v.x += g2 * s.x; v.y += g2 * s.y; v.z += g2 * s.z; v.w += g2 * s.w;
    }
    *(float4*)(out + (size_t)tok * Dq + off) = v;
}

// ---------------- launch ----------------
extern "C" void kernel_launch(void* const* d_in, const int* in_sizes, int n_in,
                              void* d_out, int out_size)
{
    const float* x  = (const float*)d_in[0];
    const float* wg = (const float*)d_in[1];
    const float* w1 = (const float*)d_in[2];
    const float* b1 = (const float*)d_in[3];
    const float* w2 = (const float*)d_in[4];
    const float* b2 = (const float*)d_in[5];
    const float* rp = (const float*)d_in[6];
    float* out = (float*)d_out;

    cudaFuncSetAttribute(ffn_mma<1>, cudaFuncAttributeMaxDynamicSharedMemorySize, SMEM_FFN);
    cudaFuncSetAttribute(ffn_mma<2>, cudaFuncAttributeMaxDynamicSharedMemorySize, SMEM_FFN);

    init_kernel<<<1, 64>>>();
    gating_kernel<<<NTOK/8, 256>>>(x, wg, rp);
    scan_kernel<<<1, 64>>>(out, out_size);

    ffn_mma<1><<<dim3(Hq/128, 3, Eq*Bq), 256, SMEM_FFN>>>(x, w1, b1);
    ffn_mma<2><<<dim3(Dq/128, 3, Eq*Bq), 256, SMEM_FFN>>>(nullptr, w2, b2);

    combine_kernel<<<NTOK, 256>>>(out);
}